// round 15
// baseline (speedup 1.0000x reference)
#include <cuda_runtime.h>
#include <cstdint>

// ---------------------------------------------------------------------------
// FPNAttentionV2, single fused launch. R13 operand-delivery structure
// (coalesced LDG -> STS.128 -> kperm LDS.128 fragments) + software pipeline:
// double-buffered smem tiles, ONE __syncthreads per k-chunk, gmem loads for
// chunk kt+1 split in halves interleaved with the two MMA h-phases of chunk
// kt so register staging peaks at 16 regs (no spills).
//
// TF32 mma.sync m16n8k8, CTA tile 128px x (128|64)och x BK=32, 256 threads,
// 8 warps 4(M) x 2(N), 2 CTAs/SM. kperm(k)=(k%4)*8+k/4, row stride 36 words.
// ---------------------------------------------------------------------------

#define CC 256
#define PAD 36
#define TILE (128 * PAD)                 // words per (X|W) buffer
#define SMEMB (4 * TILE * 4)             // X0,X1,W0,W1 = 73728 B

__device__ __forceinline__ uint32_t f2tf32(float f) {
    uint32_t r;
    asm("cvt.rna.tf32.f32 %0, %1;" : "=r"(r) : "f"(f));
    return r;
}

__device__ __forceinline__ void mma_tf32(float* c, const uint32_t* a, const uint32_t* b) {
    asm volatile(
        "mma.sync.aligned.m16n8k8.row.col.f32.tf32.tf32.f32 "
        "{%0,%1,%2,%3}, {%4,%5,%6,%7}, {%8,%9}, {%0,%1,%2,%3};"
        : "+f"(c[0]), "+f"(c[1]), "+f"(c[2]), "+f"(c[3])
        : "r"(a[0]), "r"(a[1]), "r"(a[2]), "r"(a[3]), "r"(b[0]), "r"(b[1]));
}

// One h-phase (K=16) of a 128 x (NT*16)-warp-tiled MMA. acc[mt*NT + nt][4].
template <int NT>
__device__ __forceinline__ void mma_h(
    const uint32_t* __restrict__ Xp, const uint32_t* __restrict__ Wp,
    float (*acc)[4], int h, int wm, int wn, int tg, int gp) {
    uint4 af[2][2];
#pragma unroll
    for (int mt = 0; mt < 2; ++mt) {
        int row = wm * 32 + mt * 16 + gp;
        af[mt][0] = *reinterpret_cast<const uint4*>(&Xp[row * PAD + tg * 8 + h * 4]);
        af[mt][1] = *reinterpret_cast<const uint4*>(&Xp[(row + 8) * PAD + tg * 8 + h * 4]);
    }
#pragma unroll
    for (int nh = 0; nh < NT / 4; ++nh) {
        uint4 bf[4];
#pragma unroll
        for (int n4 = 0; n4 < 4; ++n4) {
            int col = wn * (NT * 8) + (nh * 4 + n4) * 8 + gp;
            bf[n4] = *reinterpret_cast<const uint4*>(&Wp[col * PAD + tg * 8 + h * 4]);
        }
#pragma unroll
        for (int s = 0; s < 2; ++s) {
#pragma unroll
            for (int mt = 0; mt < 2; ++mt) {
                const uint32_t* a0 = reinterpret_cast<const uint32_t*>(&af[mt][0]);
                const uint32_t* a1 = reinterpret_cast<const uint32_t*>(&af[mt][1]);
                uint32_t a[4] = {a0[2 * s], a1[2 * s], a0[2 * s + 1], a1[2 * s + 1]};
#pragma unroll
                for (int n4 = 0; n4 < 4; ++n4) {
                    const uint32_t* bw = reinterpret_cast<const uint32_t*>(&bf[n4]);
                    uint32_t bq[2] = {bw[2 * s], bw[2 * s + 1]};
                    mma_tf32(acc[mt * NT + nh * 4 + n4], a, bq);
                }
            }
        }
    }
}

struct ConvSet {
    const float* w[4];
    const float* b[4];
    float* out[4];
};

struct AllArgs {
    const float* x1;
    const float* x2;
    const float* kd_w;
    const float* kd_b;
    float* kdn;
    ConvSet cs1;
    ConvSet cs2;
};

// ---- conv1x1 body: pipelined, 1 sync/kt -----------------------------------
__device__ __forceinline__ void conv1x1_body(
    const float* __restrict__ x, const ConvSet& cs, int HW,
    int bx, int by, int bb, bool ups_mode, uint32_t* __restrict__ sm) {
    uint32_t* Xb[2] = {sm, sm + TILE};
    uint32_t* Wb[2] = {sm + 2 * TILE, sm + 3 * TILE};

    const int tid  = threadIdx.x;
    const int lane = tid & 31;
    const int warp = tid >> 5;
    const int wm = warp >> 1, wn = warp & 1;
    const int tg = lane & 3, gp = lane >> 2;

    const int pt  = bx * 128;
    const int cid = by >> 1;
    const int ot  = (by & 1) * 128;

    const float* xb   = x + (size_t)bb * CC * HW;
    const float* wptr = cs.w[cid];
    const float* bptr = cs.b[cid];
    float* out        = cs.out[cid];

    const int p  = tid & 127;
    const int t7 = tid >> 7;
    const int wo = tid >> 3;
    const int cq = tid & 7;

    float acc[16][4];
#pragma unroll
    for (int i = 0; i < 16; ++i)
#pragma unroll
        for (int j = 0; j < 4; ++j) acc[i][j] = 0.f;

    // half = 0: j in {0,1}; half = 1: j in {2,3}
    auto ldgXh = [&](int kt, int half, float* xr8) {
#pragma unroll
        for (int jj = 0; jj < 2; ++jj) {
            int q = 2 * (half * 2 + jj) + t7;
#pragma unroll
            for (int r = 0; r < 4; ++r) {
                int kp = q * 4 + r;
                int k = ((kp & 7) << 2) + (kp >> 3);
                xr8[jj * 4 + r] = __ldg(&xb[(size_t)(kt * 32 + k) * HW + pt + p]);
            }
        }
    };
    auto stXh = [&](int half, const float* xr8, uint32_t* Xd) {
#pragma unroll
        for (int jj = 0; jj < 2; ++jj) {
            int q = 2 * (half * 2 + jj) + t7;
            *reinterpret_cast<uint4*>(&Xd[p * PAD + q * 4]) =
                make_uint4(f2tf32(xr8[jj * 4]), f2tf32(xr8[jj * 4 + 1]),
                           f2tf32(xr8[jj * 4 + 2]), f2tf32(xr8[jj * 4 + 3]));
        }
    };
    auto ldgWh = [&](int kt, int half, float4* wr2) {
#pragma unroll
        for (int jj = 0; jj < 2; ++jj) {
            int o = (half * 2 + jj) * 32 + wo;
            wr2[jj] = *reinterpret_cast<const float4*>(
                wptr + (size_t)(ot + o) * CC + kt * 32 + cq * 4);
        }
    };
    auto stWh = [&](int half, const float4* wr2, uint32_t* Wd) {
#pragma unroll
        for (int jj = 0; jj < 2; ++jj) {
            int o = (half * 2 + jj) * 32 + wo;
            Wd[o * PAD + 0 + cq]  = f2tf32(wr2[jj].x);
            Wd[o * PAD + 8 + cq]  = f2tf32(wr2[jj].y);
            Wd[o * PAD + 16 + cq] = f2tf32(wr2[jj].z);
            Wd[o * PAD + 24 + cq] = f2tf32(wr2[jj].w);
        }
    };

    // prologue: stage kt=0 fully
    {
        float xr8[8];
        float4 wr2[2];
#pragma unroll
        for (int half = 0; half < 2; ++half) {
            ldgXh(0, half, xr8);
            stXh(half, xr8, Xb[0]);
            ldgWh(0, half, wr2);
            stWh(half, wr2, Wb[0]);
        }
    }
    __syncthreads();

    for (int kt = 0; kt < 8; ++kt) {
        const uint32_t* Xc = Xb[kt & 1];
        const uint32_t* Wc = Wb[kt & 1];
        uint32_t* Xn = Xb[(kt & 1) ^ 1];
        uint32_t* Wn = Wb[(kt & 1) ^ 1];
        const bool pf = (kt < 7);

        float xr8[8];
        float4 wr2[2];
        if (pf) { ldgXh(kt + 1, 0, xr8); ldgWh(kt + 1, 0, wr2); }
        mma_h<8>(Xc, Wc, acc, 0, wm, wn, tg, gp);     // covers LDG latency
        if (pf) { stXh(0, xr8, Xn); stWh(0, wr2, Wn); }

        if (pf) { ldgXh(kt + 1, 1, xr8); ldgWh(kt + 1, 1, wr2); }
        mma_h<8>(Xc, Wc, acc, 1, wm, wn, tg, gp);
        if (pf) { stXh(1, xr8, Xn); stWh(1, wr2, Wn); }
        __syncthreads();
    }

    // ---- epilogue: bias + BHWC store ----
#pragma unroll
    for (int nt = 0; nt < 8; ++nt) {
        int o = ot + wn * 64 + nt * 8 + tg * 2;
        float b0 = __ldg(&bptr[o]);
        float b1 = __ldg(&bptr[o + 1]);
#pragma unroll
        for (int mt = 0; mt < 2; ++mt) {
#pragma unroll
            for (int hr = 0; hr < 2; ++hr) {
                int pg = pt + wm * 32 + mt * 16 + gp + hr * 8;
                float2 r;
                r.x = acc[mt * 8 + nt][hr * 2 + 0] + b0;
                r.y = acc[mt * 8 + nt][hr * 2 + 1] + b1;
                if (ups_mode && cid == 3) {
                    int hh = pg >> 6, wc = pg & 63;
                    float* base = out +
                        ((size_t)bb * 16384 + (size_t)(2 * hh) * 128 + 2 * wc) * CC + o;
                    *reinterpret_cast<float2*>(base) = r;
                    *reinterpret_cast<float2*>(base + CC) = r;
                    *reinterpret_cast<float2*>(base + 128 * CC) = r;
                    *reinterpret_cast<float2*>(base + 128 * CC + CC) = r;
                } else {
                    *reinterpret_cast<float2*>(out + ((size_t)bb * HW + pg) * CC + o) = r;
                }
            }
        }
    }
}

// ---- conv3x3/s2 body: pipelined over 72 (kt,tap) steps, 1 sync/step -------
__device__ __forceinline__ void conv3x3_body(
    const float* __restrict__ x, const float* __restrict__ w,
    const float* __restrict__ bias, float* __restrict__ out,
    int bx, int oq, int bb, uint32_t* __restrict__ sm) {
    uint32_t* Xb[2] = {sm, sm + TILE};
    uint32_t* Wb[2] = {sm + 2 * TILE, sm + 3 * TILE};   // 64*PAD used

    const int tid  = threadIdx.x;
    const int lane = tid & 31;
    const int warp = tid >> 5;
    const int wm = warp >> 1, wn = warp & 1;
    const int tg = lane & 3, gp = lane >> 2;

    const int pt = bx * 128;
    const int ot = oq * 64;

    const float* xb = x + (size_t)bb * CC * 16384;

    const int p  = tid & 127;
    const int t7 = tid >> 7;
    const int wo = tid >> 3;
    const int cq = tid & 7;

    const int pg0 = pt + p;
    const int oh = pg0 >> 6, ow = pg0 & 63;

    float acc[8][4];
#pragma unroll
    for (int i = 0; i < 8; ++i)
#pragma unroll
        for (int j = 0; j < 4; ++j) acc[i][j] = 0.f;

    auto ldgX = [&](int it, float* xr) {
        int kt = it / 9, tap = it % 9;
        int ti = tap / 3, tj = tap % 3;
        int ih = 2 * oh - 1 + ti;
        int iw = 2 * ow - 1 + tj;
        bool ok = (ih >= 0) && (iw >= 0);
        const float* src = xb + (size_t)(kt * 32) * 16384 + ih * 128 + iw;
#pragma unroll
        for (int j = 0; j < 4; ++j) {
            int q = 2 * j + t7;
#pragma unroll
            for (int r = 0; r < 4; ++r) {
                int kp = q * 4 + r;
                int k = ((kp & 7) << 2) + (kp >> 3);
                xr[j * 4 + r] = ok ? __ldg(src + (size_t)k * 16384) : 0.f;
            }
        }
    };
    auto stX = [&](const float* xr, uint32_t* Xd) {
#pragma unroll
        for (int j = 0; j < 4; ++j) {
            int q = 2 * j + t7;
            *reinterpret_cast<uint4*>(&Xd[p * PAD + q * 4]) =
                make_uint4(f2tf32(xr[j * 4]), f2tf32(xr[j * 4 + 1]),
                           f2tf32(xr[j * 4 + 2]), f2tf32(xr[j * 4 + 3]));
        }
    };
    auto ldgW = [&](int it, float* wrv) {
        int kt = it / 9, tap = it % 9;
        int ti = tap / 3, tj = tap % 3;
#pragma unroll
        for (int j = 0; j < 2; ++j) {
            int o = j * 32 + wo;
#pragma unroll
            for (int i = 0; i < 4; ++i)
                wrv[j * 4 + i] = __ldg(
                    &w[((size_t)(ot + o) * CC + kt * 32 + cq * 4 + i) * 9 + ti * 3 + tj]);
        }
    };
    auto stW = [&](const float* wrv, uint32_t* Wd) {
#pragma unroll
        for (int j = 0; j < 2; ++j) {
            int o = j * 32 + wo;
#pragma unroll
            for (int i = 0; i < 4; ++i)
                Wd[o * PAD + i * 8 + cq] = f2tf32(wrv[j * 4 + i]);
        }
    };

    {
        float xr[16], wrv[8];
        ldgX(0, xr);
        ldgW(0, wrv);
        stX(xr, Xb[0]);
        stW(wrv, Wb[0]);
    }
    __syncthreads();

    for (int it = 0; it < 72; ++it) {
        const uint32_t* Xc = Xb[it & 1];
        const uint32_t* Wc = Wb[it & 1];
        uint32_t* Xn = Xb[(it & 1) ^ 1];
        uint32_t* Wn = Wb[(it & 1) ^ 1];
        const bool pf = (it < 71);

        float xr[16], wrv[8];
        if (pf) { ldgX(it + 1, xr); ldgW(it + 1, wrv); }
        mma_h<4>(Xc, Wc, acc, 0, wm, wn, tg, gp);     // covers gather latency
        if (pf) { stX(xr, Xn); stW(wrv, Wn); }
        mma_h<4>(Xc, Wc, acc, 1, wm, wn, tg, gp);
        __syncthreads();
    }

#pragma unroll
    for (int nt = 0; nt < 4; ++nt) {
        int o = ot + wn * 32 + nt * 8 + tg * 2;
        float b0 = __ldg(&bias[o]);
        float b1 = __ldg(&bias[o + 1]);
#pragma unroll
        for (int mt = 0; mt < 2; ++mt) {
#pragma unroll
            for (int hr = 0; hr < 2; ++hr) {
                int pg = pt + wm * 32 + mt * 16 + gp + hr * 8;
                float2 r;
                r.x = acc[mt * 4 + nt][hr * 2 + 0] + b0;
                r.y = acc[mt * 4 + nt][hr * 2 + 1] + b1;
                *reinterpret_cast<float2*>(out + ((size_t)bb * 4096 + pg) * CC + o) = r;
            }
        }
    }
}

// ---- the single fused kernel ----------------------------------------------
// CTA ranges: [0,256) conv3x3 (deepest first); [256,1792) x1; [1792,2304) x2.
__global__ __launch_bounds__(256, 2) void fused_all(AllArgs A) {
    extern __shared__ uint32_t sm[];

    const int bid = blockIdx.x;
    if (bid < 256) {
        int t = bid;
        int bx = t & 31; t >>= 5;
        int oq = t & 3;
        int bb = t >> 2;
        conv3x3_body(A.x1, A.kd_w, A.kd_b, A.kdn, bx, oq, bb, sm);
    } else if (bid < 1792) {
        int t = bid - 256;
        int bx = t % 128; t /= 128;
        int by = t % 6;
        int bb = t / 6;
        conv1x1_body(A.x1, A.cs1, 16384, bx, by, bb, false, sm);
    } else {
        int t = bid - 1792;
        int bx = t & 31; t >>= 5;
        int by = t & 7;
        int bb = t >> 3;
        conv1x1_body(A.x2, A.cs2, 4096, bx, by, bb, true, sm);
    }
}

extern "C" void kernel_launch(void* const* d_in, const int* in_sizes, int n_in,
                              void* d_out, int out_size) {
    const float* x1 = (const float*)d_in[0];
    const float* x2 = (const float*)d_in[1];
    const float* q1_w = (const float*)d_in[2];
    const float* q1_b = (const float*)d_in[3];
    const float* q2_w = (const float*)d_in[4];
    const float* q2_b = (const float*)d_in[5];
    const float* ks1_w = (const float*)d_in[6];
    const float* ks1_b = (const float*)d_in[7];
    const float* ks2_w = (const float*)d_in[8];
    const float* ks2_b = (const float*)d_in[9];
    const float* kup_w = (const float*)d_in[10];
    const float* kup_b = (const float*)d_in[11];
    const float* v1_w = (const float*)d_in[12];
    const float* v1_b = (const float*)d_in[13];
    const float* v2_w = (const float*)d_in[14];
    const float* v2_b = (const float*)d_in[15];
    const float* kd_w = (const float*)d_in[16];
    const float* kd_b = (const float*)d_in[17];

    float* out = (float*)d_out;
    float* q1  = out;                    // 2*128*128*256
    float* q2  = out + 8388608;          // 2*64*64*256
    float* kup = out + 10485760;         // 2*128*128*256 (upsampled)
    float* ks1 = out + 18874368;
    float* ks2 = out + 27262976;
    float* kdn = out + 29360128;
    float* v1  = out + 31457280;
    float* v2  = out + 39845888;

    AllArgs A;
    A.x1 = x1; A.x2 = x2; A.kd_w = kd_w; A.kd_b = kd_b; A.kdn = kdn;

    A.cs1.w[0] = q1_w;  A.cs1.b[0] = q1_b;  A.cs1.out[0] = q1;
    A.cs1.w[1] = ks1_w; A.cs1.b[1] = ks1_b; A.cs1.out[1] = ks1;
    A.cs1.w[2] = v1_w;  A.cs1.b[2] = v1_b;  A.cs1.out[2] = v1;
    A.cs1.w[3] = q1_w;  A.cs1.b[3] = q1_b;  A.cs1.out[3] = q1;  // unused

    A.cs2.w[0] = q2_w;  A.cs2.b[0] = q2_b;  A.cs2.out[0] = q2;
    A.cs2.w[1] = ks2_w; A.cs2.b[1] = ks2_b; A.cs2.out[1] = ks2;
    A.cs2.w[2] = v2_w;  A.cs2.b[2] = v2_b;  A.cs2.out[2] = v2;
    A.cs2.w[3] = kup_w; A.cs2.b[3] = kup_b; A.cs2.out[3] = kup;

    static bool attr_done = false;
    if (!attr_done) {
        cudaFuncSetAttribute(fused_all,
                             cudaFuncAttributeMaxDynamicSharedMemorySize, SMEMB);
        attr_done = true;
    }
    fused_all<<<dim3(2304, 1, 1), dim3(256), SMEMB>>>(A);
}

// round 17
// speedup vs baseline: 1.0262x; 1.0262x over previous
#include <cuda_runtime.h>
#include <cstdint>

// ---------------------------------------------------------------------------
// FPNAttentionV2, single fused launch (R13 structure) + two fixes:
//  1) W-STS bank-conflict-free thread->o remap (within-warp o spacing 2).
//  2) Triple-buffered smem tiles, ONE __syncthreads per k-chunk
//     (ldg+sts(kt+1) -> sync -> mma(kt); distance-3 buffer reuse).
// Staging registers die at the STS (before the barrier) — the R13 liveness
// pattern that ptxas compiles without spills.
//
// TF32 mma.sync m16n8k8, CTA tile 128px x (128|64)och x BK=32, 256 threads,
// 8 warps 4(M) x 2(N), 2 CTAs/SM. kperm(k)=(k%4)*8+k/4, row stride 36 words.
// ---------------------------------------------------------------------------

#define CC 256
#define PAD 36
#define TILE (128 * PAD)          // 4608 words per buffer
#define SMEMB (6 * TILE * 4)      // X0..X2, W0..W2 = 110592 B

__device__ __forceinline__ uint32_t f2tf32(float f) {
    uint32_t r;
    asm("cvt.rna.tf32.f32 %0, %1;" : "=r"(r) : "f"(f));
    return r;
}

__device__ __forceinline__ void mma_tf32(float* c, const uint32_t* a, const uint32_t* b) {
    asm volatile(
        "mma.sync.aligned.m16n8k8.row.col.f32.tf32.tf32.f32 "
        "{%0,%1,%2,%3}, {%4,%5,%6,%7}, {%8,%9}, {%0,%1,%2,%3};"
        : "+f"(c[0]), "+f"(c[1]), "+f"(c[2]), "+f"(c[3])
        : "r"(a[0]), "r"(a[1]), "r"(a[2]), "r"(a[3]), "r"(b[0]), "r"(b[1]));
}

// One 128 x (NT*16) x 32 tile MMA phase. acc indexed [mt*NT + nt][4].
template <int NT>
__device__ __forceinline__ void mma_phase(
    const uint32_t* __restrict__ Xp, const uint32_t* __restrict__ Wp,
    float (*acc)[4], int wm, int wn, int tg, int gp) {
#pragma unroll
    for (int h = 0; h < 2; ++h) {
        uint4 af[2][2], bf[NT];
#pragma unroll
        for (int mt = 0; mt < 2; ++mt) {
            int row = wm * 32 + mt * 16 + gp;
            af[mt][0] = *reinterpret_cast<const uint4*>(&Xp[row * PAD + tg * 8 + h * 4]);
            af[mt][1] = *reinterpret_cast<const uint4*>(&Xp[(row + 8) * PAD + tg * 8 + h * 4]);
        }
#pragma unroll
        for (int nt = 0; nt < NT; ++nt) {
            int col = wn * (NT * 8) + nt * 8 + gp;
            bf[nt] = *reinterpret_cast<const uint4*>(&Wp[col * PAD + tg * 8 + h * 4]);
        }
#pragma unroll
        for (int s = 0; s < 2; ++s) {
#pragma unroll
            for (int mt = 0; mt < 2; ++mt) {
                const uint32_t* a0 = reinterpret_cast<const uint32_t*>(&af[mt][0]);
                const uint32_t* a1 = reinterpret_cast<const uint32_t*>(&af[mt][1]);
                uint32_t a[4] = {a0[2 * s], a1[2 * s], a0[2 * s + 1], a1[2 * s + 1]};
#pragma unroll
                for (int nt = 0; nt < NT; ++nt) {
                    const uint32_t* bw = reinterpret_cast<const uint32_t*>(&bf[nt]);
                    uint32_t bq[2] = {bw[2 * s], bw[2 * s + 1]};
                    mma_tf32(acc[mt * NT + nt], a, bq);
                }
            }
        }
    }
}

struct ConvSet {
    const float* w[4];
    const float* b[4];
    float* out[4];
};

struct AllArgs {
    const float* x1;
    const float* x2;
    const float* kd_w;
    const float* kd_b;
    float* kdn;
    ConvSet cs1;
    ConvSet cs2;
};

// ---- conv1x1 body ---------------------------------------------------------
__device__ __forceinline__ void conv1x1_body(
    const float* __restrict__ x, const ConvSet& cs, int HW,
    int bx, int by, int bb, bool ups_mode, uint32_t* __restrict__ sm) {
    const int tid  = threadIdx.x;
    const int lane = tid & 31;
    const int warp = tid >> 5;
    const int wm = warp >> 1, wn = warp & 1;
    const int tg = lane & 3, gp = lane >> 2;

    const int pt  = bx * 128;
    const int cid = by >> 1;
    const int ot  = (by & 1) * 128;

    const float* xb   = x + (size_t)bb * CC * HW;
    const float* wptr = cs.w[cid];
    const float* bptr = cs.b[cid];
    float* out        = cs.out[cid];

    const int p  = tid & 127;
    const int t7 = tid >> 7;
    // conflict-free W map: within-warp o spacing 2 -> bank stride 8
    const int omap = ((tid >> 3) & 3) * 2 + (warp & 1) + ((warp >> 1) << 3);
    const int cq = tid & 7;

    uint32_t* Xc = sm;             uint32_t* Wc = sm + 3 * TILE;
    uint32_t* Xn = sm + TILE;      uint32_t* Wn = sm + 4 * TILE;
    uint32_t* Xf = sm + 2 * TILE;  uint32_t* Wf = sm + 5 * TILE;

    float acc[16][4];
#pragma unroll
    for (int i = 0; i < 16; ++i)
#pragma unroll
        for (int j = 0; j < 4; ++j) acc[i][j] = 0.f;

    auto stage = [&](int kt, uint32_t* Xd, uint32_t* Wd) {
        float xr[16];
#pragma unroll
        for (int j = 0; j < 4; ++j) {
            int q = 2 * j + t7;
#pragma unroll
            for (int r = 0; r < 4; ++r) {
                int kp = q * 4 + r;
                int k = ((kp & 7) << 2) + (kp >> 3);
                xr[j * 4 + r] = __ldg(&xb[(size_t)(kt * 32 + k) * HW + pt + p]);
            }
        }
        float4 wr[4];
#pragma unroll
        for (int j = 0; j < 4; ++j)
            wr[j] = *reinterpret_cast<const float4*>(
                wptr + (size_t)(ot + j * 32 + omap) * CC + kt * 32 + cq * 4);

#pragma unroll
        for (int j = 0; j < 4; ++j) {
            int q = 2 * j + t7;
            *reinterpret_cast<uint4*>(&Xd[p * PAD + q * 4]) =
                make_uint4(f2tf32(xr[j * 4]), f2tf32(xr[j * 4 + 1]),
                           f2tf32(xr[j * 4 + 2]), f2tf32(xr[j * 4 + 3]));
        }
#pragma unroll
        for (int j = 0; j < 4; ++j) {
            int o = j * 32 + omap;
            Wd[o * PAD + 0 + cq]  = f2tf32(wr[j].x);
            Wd[o * PAD + 8 + cq]  = f2tf32(wr[j].y);
            Wd[o * PAD + 16 + cq] = f2tf32(wr[j].z);
            Wd[o * PAD + 24 + cq] = f2tf32(wr[j].w);
        }
    };

    stage(0, Xc, Wc);              // prologue (covered by iter-0 sync)
    for (int kt = 0; kt < 8; ++kt) {
        if (kt < 7) stage(kt + 1, Xn, Wn);
        __syncthreads();
        mma_phase<8>(Xc, Wc, acc, wm, wn, tg, gp);
        // rotate cur <- nxt <- fut <- cur
        uint32_t* tx = Xc; Xc = Xn; Xn = Xf; Xf = tx;
        uint32_t* tw = Wc; Wc = Wn; Wn = Wf; Wf = tw;
    }

    // ---- epilogue: bias + BHWC store ----
#pragma unroll
    for (int nt = 0; nt < 8; ++nt) {
        int o = ot + wn * 64 + nt * 8 + tg * 2;
        float b0 = __ldg(&bptr[o]);
        float b1 = __ldg(&bptr[o + 1]);
#pragma unroll
        for (int mt = 0; mt < 2; ++mt) {
#pragma unroll
            for (int hr = 0; hr < 2; ++hr) {
                int pg = pt + wm * 32 + mt * 16 + gp + hr * 8;
                float2 r;
                r.x = acc[mt * 8 + nt][hr * 2 + 0] + b0;
                r.y = acc[mt * 8 + nt][hr * 2 + 1] + b1;
                if (ups_mode && cid == 3) {
                    int hh = pg >> 6, wc = pg & 63;
                    float* base = out +
                        ((size_t)bb * 16384 + (size_t)(2 * hh) * 128 + 2 * wc) * CC + o;
                    *reinterpret_cast<float2*>(base) = r;
                    *reinterpret_cast<float2*>(base + CC) = r;
                    *reinterpret_cast<float2*>(base + 128 * CC) = r;
                    *reinterpret_cast<float2*>(base + 128 * CC + CC) = r;
                } else {
                    *reinterpret_cast<float2*>(out + ((size_t)bb * HW + pg) * CC + o) = r;
                }
            }
        }
    }
}

// ---- conv3x3/s2 body ------------------------------------------------------
__device__ __forceinline__ void conv3x3_body(
    const float* __restrict__ x, const float* __restrict__ w,
    const float* __restrict__ bias, float* __restrict__ out,
    int bx, int oq, int bb, uint32_t* __restrict__ sm) {
    const int tid  = threadIdx.x;
    const int lane = tid & 31;
    const int warp = tid >> 5;
    const int wm = warp >> 1, wn = warp & 1;
    const int tg = lane & 3, gp = lane >> 2;

    const int pt = bx * 128;
    const int ot = oq * 64;

    const float* xb = x + (size_t)bb * CC * 16384;

    const int p  = tid & 127;
    const int t7 = tid >> 7;
    const int omap = ((tid >> 3) & 3) * 2 + (warp & 1) + ((warp >> 1) << 3);
    const int cq = tid & 7;

    const int pg0 = pt + p;
    const int oh = pg0 >> 6, ow = pg0 & 63;

    uint32_t* Xc = sm;             uint32_t* Wc = sm + 3 * TILE;
    uint32_t* Xn = sm + TILE;      uint32_t* Wn = sm + 4 * TILE;
    uint32_t* Xf = sm + 2 * TILE;  uint32_t* Wf = sm + 5 * TILE;

    float acc[8][4];
#pragma unroll
    for (int i = 0; i < 8; ++i)
#pragma unroll
        for (int j = 0; j < 4; ++j) acc[i][j] = 0.f;

    auto stage = [&](int it, uint32_t* Xd, uint32_t* Wd) {
        int kt = it / 9, tap = it % 9;
        int ti = tap / 3, tj = tap % 3;
        int ih = 2 * oh - 1 + ti;
        int iw = 2 * ow - 1 + tj;
        bool ok = (ih >= 0) && (iw >= 0);
        const float* src = xb + (size_t)(kt * 32) * 16384 + ih * 128 + iw;

        float xr[16];
#pragma unroll
        for (int j = 0; j < 4; ++j) {
            int q = 2 * j + t7;
#pragma unroll
            for (int r = 0; r < 4; ++r) {
                int kp = q * 4 + r;
                int k = ((kp & 7) << 2) + (kp >> 3);
                xr[j * 4 + r] = ok ? __ldg(src + (size_t)k * 16384) : 0.f;
            }
        }
        float wrv[8];
#pragma unroll
        for (int j = 0; j < 2; ++j) {
            int o = j * 32 + omap;
#pragma unroll
            for (int i = 0; i < 4; ++i)
                wrv[j * 4 + i] = __ldg(
                    &w[((size_t)(ot + o) * CC + kt * 32 + cq * 4 + i) * 9 + ti * 3 + tj]);
        }

#pragma unroll
        for (int j = 0; j < 4; ++j) {
            int q = 2 * j + t7;
            *reinterpret_cast<uint4*>(&Xd[p * PAD + q * 4]) =
                make_uint4(f2tf32(xr[j * 4]), f2tf32(xr[j * 4 + 1]),
                           f2tf32(xr[j * 4 + 2]), f2tf32(xr[j * 4 + 3]));
        }
#pragma unroll
        for (int j = 0; j < 2; ++j) {
            int o = j * 32 + omap;
#pragma unroll
            for (int i = 0; i < 4; ++i)
                Wd[o * PAD + i * 8 + cq] = f2tf32(wrv[j * 4 + i]);
        }
    };

    stage(0, Xc, Wc);
    for (int it = 0; it < 72; ++it) {
        if (it < 71) stage(it + 1, Xn, Wn);
        __syncthreads();
        mma_phase<4>(Xc, Wc, acc, wm, wn, tg, gp);
        uint32_t* tx = Xc; Xc = Xn; Xn = Xf; Xf = tx;
        uint32_t* tw = Wc; Wc = Wn; Wn = Wf; Wf = tw;
    }

#pragma unroll
    for (int nt = 0; nt < 4; ++nt) {
        int o = ot + wn * 32 + nt * 8 + tg * 2;
        float b0 = __ldg(&bias[o]);
        float b1 = __ldg(&bias[o + 1]);
#pragma unroll
        for (int mt = 0; mt < 2; ++mt) {
#pragma unroll
            for (int hr = 0; hr < 2; ++hr) {
                int pg = pt + wm * 32 + mt * 16 + gp + hr * 8;
                float2 r;
                r.x = acc[mt * 4 + nt][hr * 2 + 0] + b0;
                r.y = acc[mt * 4 + nt][hr * 2 + 1] + b1;
                *reinterpret_cast<float2*>(out + ((size_t)bb * 4096 + pg) * CC + o) = r;
            }
        }
    }
}

// ---- the single fused kernel ----------------------------------------------
// CTA ranges: [0,256) conv3x3 (deepest first); [256,1792) x1; [1792,2304) x2.
__global__ __launch_bounds__(256, 2) void fused_all(AllArgs A) {
    extern __shared__ uint32_t sm[];

    const int bid = blockIdx.x;
    if (bid < 256) {
        int t = bid;
        int bx = t & 31; t >>= 5;
        int oq = t & 3;
        int bb = t >> 2;
        conv3x3_body(A.x1, A.kd_w, A.kd_b, A.kdn, bx, oq, bb, sm);
    } else if (bid < 1792) {
        int t = bid - 256;
        int bx = t % 128; t /= 128;
        int by = t % 6;
        int bb = t / 6;
        conv1x1_body(A.x1, A.cs1, 16384, bx, by, bb, false, sm);
    } else {
        int t = bid - 1792;
        int bx = t & 31; t >>= 5;
        int by = t & 7;
        int bb = t >> 3;
        conv1x1_body(A.x2, A.cs2, 4096, bx, by, bb, true, sm);
    }
}

extern "C" void kernel_launch(void* const* d_in, const int* in_sizes, int n_in,
                              void* d_out, int out_size) {
    const float* x1 = (const float*)d_in[0];
    const float* x2 = (const float*)d_in[1];
    const float* q1_w = (const float*)d_in[2];
    const float* q1_b = (const float*)d_in[3];
    const float* q2_w = (const float*)d_in[4];
    const float* q2_b = (const float*)d_in[5];
    const float* ks1_w = (const float*)d_in[6];
    const float* ks1_b = (const float*)d_in[7];
    const float* ks2_w = (const float*)d_in[8];
    const float* ks2_b = (const float*)d_in[9];
    const float* kup_w = (const float*)d_in[10];
    const float* kup_b = (const float*)d_in[11];
    const float* v1_w = (const float*)d_in[12];
    const float* v1_b = (const float*)d_in[13];
    const float* v2_w = (const float*)d_in[14];
    const float* v2_b = (const float*)d_in[15];
    const float* kd_w = (const float*)d_in[16];
    const float* kd_b = (const float*)d_in[17];

    float* out = (float*)d_out;
    float* q1  = out;                    // 2*128*128*256
    float* q2  = out + 8388608;          // 2*64*64*256
    float* kup = out + 10485760;         // 2*128*128*256 (upsampled)
    float* ks1 = out + 18874368;
    float* ks2 = out + 27262976;
    float* kdn = out + 29360128;
    float* v1  = out + 31457280;
    float* v2  = out + 39845888;

    AllArgs A;
    A.x1 = x1; A.x2 = x2; A.kd_w = kd_w; A.kd_b = kd_b; A.kdn = kdn;

    A.cs1.w[0] = q1_w;  A.cs1.b[0] = q1_b;  A.cs1.out[0] = q1;
    A.cs1.w[1] = ks1_w; A.cs1.b[1] = ks1_b; A.cs1.out[1] = ks1;
    A.cs1.w[2] = v1_w;  A.cs1.b[2] = v1_b;  A.cs1.out[2] = v1;
    A.cs1.w[3] = q1_w;  A.cs1.b[3] = q1_b;  A.cs1.out[3] = q1;  // unused

    A.cs2.w[0] = q2_w;  A.cs2.b[0] = q2_b;  A.cs2.out[0] = q2;
    A.cs2.w[1] = ks2_w; A.cs2.b[1] = ks2_b; A.cs2.out[1] = ks2;
    A.cs2.w[2] = v2_w;  A.cs2.b[2] = v2_b;  A.cs2.out[2] = v2;
    A.cs2.w[3] = kup_w; A.cs2.b[3] = kup_b; A.cs2.out[3] = kup;

    static bool attr_done = false;
    if (!attr_done) {
        cudaFuncSetAttribute(fused_all,
                             cudaFuncAttributeMaxDynamicSharedMemorySize, SMEMB);
        attr_done = true;
    }
    fused_all<<<dim3(2304, 1, 1), dim3(256), SMEMB>>>(A);
}